// round 14
// baseline (speedup 1.0000x reference)
#include <cuda_runtime.h>
#include <mma.h>
#include <math.h>
#include <cstdint>

using namespace nvcuda;

#define NN      4096
#define INDIM   512
#define QKVD    512    // OUT_DIM * NUM_HEADS
#define NHEAD   8
#define ODIM    64
#define MAXNBR  512

// Scratch (allocation-free rule: __device__ globals)
__device__ float g_Q   [NN * QKVD];
__device__ float g_KV  [NN * 2 * QKVD];   // row m: [K(512) | V(512)]
__device__ float g_Tv  [QKVD];
__device__ float g_hsum[INDIM];
__device__ int   g_nbr [NN * MAXNBR];
__device__ int   g_cnt [NN];

// ---------------------------------------------------------------------------
// cp.async helpers
// ---------------------------------------------------------------------------
__device__ __forceinline__ void cpa16(float* dst, const float* src) {
    unsigned int d = (unsigned int)__cvta_generic_to_shared(dst);
    asm volatile("cp.async.cg.shared.global [%0], [%1], 16;" :: "r"(d), "l"(src));
}
__device__ __forceinline__ void cp_commit() {
    asm volatile("cp.async.commit_group;");
}
template<int N> __device__ __forceinline__ void cp_wait() {
    asm volatile("cp.async.wait_group %0;" :: "n"(N));
}

template <class Frag>
__device__ __forceinline__ void round_frag_tf32(Frag& f) {
#pragma unroll
    for (int t = 0; t < f.num_elements; t++)
        f.x[t] = wmma::__float_to_tf32(f.x[t]);
}

// ---------------------------------------------------------------------------
// Fused QKV GEMM, tf32 wmma, cp.async double-buffered, RN-rounded fragments.
// C = h @ W (+ bias via an extra MMA k-step), Q scaled by 0.125 in-register.
// BM=128 BN=128 BK=16; 8 warps, each 64x32 (4x2 fragments).
// Grid: (QKVD/BN=4, NN/BM=32, 3)
// ---------------------------------------------------------------------------
#define BM 128
#define BN 128
#define BK 16
#define LDA 20           // BK + 4 pad
#define LDB 132          // BN + 4 pad
#define STG_F (BM*LDA + BK*LDB)   // floats per stage = 2560 + 2112 = 4672

__global__ __launch_bounds__(256) void qkv_gemm_tc(
    const float* __restrict__ Hm,
    const float* __restrict__ Wq, const float* __restrict__ bq,
    const float* __restrict__ Wk, const float* __restrict__ bk,
    const float* __restrict__ Wv, const float* __restrict__ bv)
{
    __shared__ float smem[2 * STG_F];   // 37.4 KB

    const int tid = threadIdx.x;
    const int sel = blockIdx.z;
    const int n0  = blockIdx.x * BN;
    const int m0  = blockIdx.y * BM;

    const float* W    = (sel == 0) ? Wq : (sel == 1) ? Wk : Wv;
    const float* bias = (sel == 0) ? bq : (sel == 1) ? bk : bv;
    float* C; int ldc;
    if (sel == 0)      { C = g_Q;         ldc = QKVD;     }
    else if (sel == 1) { C = g_KV;        ldc = 2 * QKVD; }
    else               { C = g_KV + QKVD; ldc = 2 * QKVD; }

    const int wid = tid >> 5;
    const int wr  = wid >> 2;    // 0..1  (64-row slab)
    const int wc  = wid & 3;     // 0..3  (32-col slab)

    wmma::fragment<wmma::accumulator, 16, 16, 8, float> acc[4][2];
#pragma unroll
    for (int i = 0; i < 4; i++)
#pragma unroll
        for (int j = 0; j < 2; j++) wmma::fill_fragment(acc[i][j], 0.0f);

    // async stage loader: A 128x16, B 16x128 (512 float4 each, 2/thread)
    auto loadStage = [&](int buf, int k0) {
        float* As = smem + buf * STG_F;
        float* Bs = As + BM * LDA;
#pragma unroll
        for (int q = 0; q < 2; q++) {
            int idx = tid + q * 256;
            int r = idx >> 2, c4 = (idx & 3) * 4;
            cpa16(As + r * LDA + c4, Hm + (size_t)(m0 + r) * INDIM + k0 + c4);
        }
#pragma unroll
        for (int q = 0; q < 2; q++) {
            int idx = tid + q * 256;
            int r = idx >> 5, c4 = (idx & 31) * 4;
            cpa16(Bs + r * LDB + c4, W + (size_t)(k0 + r) * QKVD + n0 + c4);
        }
        cp_commit();
    };

    loadStage(0, 0);
    int buf = 0;
#pragma unroll 1
    for (int it = 0; it < INDIM / BK; ++it) {
        if (it + 1 < INDIM / BK) { loadStage(buf ^ 1, (it + 1) * BK); cp_wait<1>(); }
        else                     { cp_wait<0>(); }
        __syncthreads();

        const float* As = smem + buf * STG_F;
        const float* Bs = As + BM * LDA;
#pragma unroll
        for (int kk = 0; kk < BK; kk += 8) {
            wmma::fragment<wmma::matrix_a, 16, 16, 8, wmma::precision::tf32, wmma::row_major> af[4];
            wmma::fragment<wmma::matrix_b, 16, 16, 8, wmma::precision::tf32, wmma::row_major> bf[2];
#pragma unroll
            for (int i = 0; i < 4; i++) {
                wmma::load_matrix_sync(af[i], As + (wr * 64 + i * 16) * LDA + kk, LDA);
                round_frag_tf32(af[i]);
            }
#pragma unroll
            for (int j = 0; j < 2; j++) {
                wmma::load_matrix_sync(bf[j], Bs + kk * LDB + wc * 32 + j * 16, LDB);
                round_frag_tf32(bf[j]);
            }
#pragma unroll
            for (int i = 0; i < 4; i++)
#pragma unroll
                for (int j = 0; j < 2; j++)
                    wmma::mma_sync(acc[i][j], af[i], bf[j], acc[i][j]);
        }
        __syncthreads();
        buf ^= 1;
    }

    // Bias as one extra MMA k-step: A chunk = ones column, B chunk row0 = bias.
    {
        float* As = smem;
        float* Bs = smem + BM * LDA;
        for (int idx = tid; idx < BM * 8; idx += 256) {
            int r = idx >> 3, c = idx & 7;
            As[r * LDA + c] = (c == 0) ? 1.0f : 0.0f;
        }
        for (int idx = tid; idx < 8 * BN; idx += 256) {
            int r = idx >> 7, c = idx & 127;
            Bs[r * LDB + c] = (r == 0) ? bias[n0 + c] : 0.0f;
        }
        __syncthreads();
        wmma::fragment<wmma::matrix_a, 16, 16, 8, wmma::precision::tf32, wmma::row_major> af[4];
        wmma::fragment<wmma::matrix_b, 16, 16, 8, wmma::precision::tf32, wmma::row_major> bf[2];
#pragma unroll
        for (int i = 0; i < 4; i++)
            wmma::load_matrix_sync(af[i], As + (wr * 64 + i * 16) * LDA, LDA);
#pragma unroll
        for (int j = 0; j < 2; j++) {
            wmma::load_matrix_sync(bf[j], Bs + wc * 32 + j * 16, LDB);
            round_frag_tf32(bf[j]);
        }
#pragma unroll
        for (int i = 0; i < 4; i++)
#pragma unroll
            for (int j = 0; j < 2; j++)
                wmma::mma_sync(acc[i][j], af[i], bf[j], acc[i][j]);
    }

    if (sel == 0) {   // Q scaling folds into fragment registers
#pragma unroll
        for (int i = 0; i < 4; i++)
#pragma unroll
            for (int j = 0; j < 2; j++)
#pragma unroll
                for (int t = 0; t < acc[i][j].num_elements; t++)
                    acc[i][j].x[t] *= 0.125f;
    }

#pragma unroll
    for (int i = 0; i < 4; i++)
#pragma unroll
        for (int j = 0; j < 2; j++)
            wmma::store_matrix_sync(
                C + (size_t)(m0 + wr * 64 + i * 16) * ldc + n0 + wc * 32 + j * 16,
                acc[i][j], ldc, wmma::mem_row_major);
}

// ---------------------------------------------------------------------------
// Deterministic adjacency compaction: one warp per row, ballot prefix.
// ---------------------------------------------------------------------------
__global__ __launch_bounds__(256) void scan_A(const float* __restrict__ A)
{
    const int lane = threadIdx.x & 31;
    const int wid  = threadIdx.x >> 5;
    const int n    = blockIdx.x * 8 + wid;

    const float4* Arow = (const float4*)(A + (size_t)n * NN);
    int* nb = g_nbr + (size_t)n * MAXNBR;
    const unsigned lmask = (1u << lane) - 1u;
    int cnt = 0;

#pragma unroll 4
    for (int j = 0; j < NN / 128; ++j) {
        float4 v = Arow[lane + 32 * j];
        float vs[4] = {v.x, v.y, v.z, v.w};
#pragma unroll
        for (int e = 0; e < 4; e++) {
            bool nz = (vs[e] != 0.0f);
            unsigned msk = __ballot_sync(0xffffffffu, nz);
            if (nz) {
                int pos = cnt + __popc(msk & lmask);
                if (pos < MAXNBR) nb[pos] = 128 * j + 4 * lane + e;
            }
            cnt += __popc(msk);
        }
    }
    if (lane == 0) g_cnt[n] = min(cnt, MAXNBR);
}

// ---------------------------------------------------------------------------
// Tv via algebra: Tv = (sum_m h[m,:]) @ Wv + NN * bv  (fp32-exact path,
// independent of the GEMM -> off the critical path).
// ---------------------------------------------------------------------------
__global__ void init_zero_kernel() {
    int c = blockIdx.x * 256 + threadIdx.x;
    if (c < QKVD) g_Tv[c] = 0.f;
    else if (c < QKVD + INDIM) g_hsum[c - QKVD] = 0.f;
}

__global__ __launch_bounds__(256) void hsum_kernel(const float* __restrict__ Hm)
{
    // 256 blocks x 16 rows; thread t owns columns 2t, 2t+1 (float2, coalesced)
    const int c0 = threadIdx.x * 2;
    const int r0 = blockIdx.x * 16;
    float s0 = 0.f, s1 = 0.f;
#pragma unroll 4
    for (int r = r0; r < r0 + 16; r++) {
        float2 v = *(const float2*)(Hm + (size_t)r * INDIM + c0);
        s0 += v.x; s1 += v.y;
    }
    atomicAdd(&g_hsum[c0 + 0], s0);
    atomicAdd(&g_hsum[c0 + 1], s1);
}

__global__ __launch_bounds__(512) void tv_matvec_kernel(
    const float* __restrict__ Wv, const float* __restrict__ bv)
{
    const int c  = threadIdx.x;               // 512 threads = all columns
    const int k0 = blockIdx.x * 32;           // 16 blocks x 32 k-slices
    float s = 0.f;
#pragma unroll 8
    for (int k = k0; k < k0 + 32; k++)
        s = fmaf(g_hsum[k], Wv[(size_t)k * QKVD + c], s);
    if (blockIdx.x == 0) s = fmaf((float)NN, bv[c], s);
    atomicAdd(&g_Tv[c], s);
}

// ---------------------------------------------------------------------------
// Edge attention. One 128-thread block per row n; pure edge work (A pre-
// compacted). Lane l, chunk j covers columns c = 4l + 128j + e; head(c) =
// (4l+e)%8 is j-invariant, so softmax weights apply elementwise.
// ---------------------------------------------------------------------------
__global__ __launch_bounds__(128) void attn_kernel(float* __restrict__ out)
{
    __shared__ float accs[QKVD];

    const int n    = blockIdx.x;
    const int tid  = threadIdx.x;
    const int lane = tid & 31;
    const int wid  = tid >> 5;

    for (int i = tid; i < QKVD; i += 128) accs[i] = 0.f;

    const float4* Q4 = (const float4*)g_Q + (size_t)n * 128;
    float4 qv[4];
#pragma unroll
    for (int j = 0; j < 4; j++) qv[j] = Q4[lane + 32 * j];

    __syncthreads();
    const int  count = g_cnt[n];
    const int* nb    = g_nbr + (size_t)n * MAXNBR;

    float4 vacc[4];
#pragma unroll
    for (int j = 0; j < 4; j++) vacc[j] = make_float4(0.f, 0.f, 0.f, 0.f);

    for (int i = wid; i < count; i += 4) {
        const int m = nb[i];
        const float4* KV = (const float4*)g_KV + (size_t)m * 256;

        float4 kv[4], vv[4];
#pragma unroll
        for (int j = 0; j < 4; j++) kv[j] = KV[lane + 32 * j];
#pragma unroll
        for (int j = 0; j < 4; j++) vv[j] = KV[128 + lane + 32 * j];  // issue early

        float4 s = make_float4(0.f, 0.f, 0.f, 0.f);
#pragma unroll
        for (int j = 0; j < 4; j++) {
            s.x = fmaf(qv[j].x, kv[j].x, s.x);
            s.y = fmaf(qv[j].y, kv[j].y, s.y);
            s.z = fmaf(qv[j].z, kv[j].z, s.z);
            s.w = fmaf(qv[j].w, kv[j].w, s.w);
        }
#pragma unroll
        for (int off = 2; off < 32; off <<= 1) {
            s.x += __shfl_xor_sync(0xffffffffu, s.x, off);
            s.y += __shfl_xor_sync(0xffffffffu, s.y, off);
            s.z += __shfl_xor_sync(0xffffffffu, s.z, off);
            s.w += __shfl_xor_sync(0xffffffffu, s.w, off);
        }
        float mymax = fmaxf(fmaxf(s.x, s.y), fmaxf(s.z, s.w));
        float gmax  = fmaxf(mymax, __shfl_xor_sync(0xffffffffu, mymax, 1));
        float4 ex;
        ex.x = __expf(s.x - gmax);
        ex.y = __expf(s.y - gmax);
        ex.z = __expf(s.z - gmax);
        ex.w = __expf(s.w - gmax);
        float mysum = ex.x + ex.y + ex.z + ex.w;
        float tot   = mysum + __shfl_xor_sync(0xffffffffu, mysum, 1);
        const float inv = 1.0f / tot;
        float4 w;
        w.x = ex.x * inv - 0.125f;
        w.y = ex.y * inv - 0.125f;
        w.z = ex.z * inv - 0.125f;
        w.w = ex.w * inv - 0.125f;

#pragma unroll
        for (int j = 0; j < 4; j++) {
            vacc[j].x = fmaf(w.x, vv[j].x, vacc[j].x);
            vacc[j].y = fmaf(w.y, vv[j].y, vacc[j].y);
            vacc[j].z = fmaf(w.z, vv[j].z, vacc[j].z);
            vacc[j].w = fmaf(w.w, vv[j].w, vacc[j].w);
        }
    }

#pragma unroll
    for (int j = 0; j < 4; j++) {
        const int c = 4 * lane + 128 * j;
        atomicAdd(&accs[c + 0], vacc[j].x);
        atomicAdd(&accs[c + 1], vacc[j].y);
        atomicAdd(&accs[c + 2], vacc[j].z);
        atomicAdd(&accs[c + 3], vacc[j].w);
    }
    __syncthreads();

    for (int t = tid; t < QKVD; t += 128) {
        const int d = t & 63;
        const int h = t >> 6;
        const int c = d * 8 + h;
        out[(size_t)h * (NN * ODIM) + (size_t)n * ODIM + d] =
            0.125f * g_Tv[c] + accs[c];
    }
}

// ---------------------------------------------------------------------------
extern "C" void kernel_launch(void* const* d_in, const int* in_sizes, int n_in,
                              void* d_out, int out_size)
{
    const float* A  = (const float*)d_in[0];
    const float* h  = (const float*)d_in[1];
    const float* Wq = (const float*)d_in[2];
    const float* bq = (const float*)d_in[3];
    const float* Wk = (const float*)d_in[4];
    const float* bk = (const float*)d_in[5];
    const float* Wv = (const float*)d_in[6];
    const float* bv = (const float*)d_in[7];
    float* out = (float*)d_out;

    init_zero_kernel<<<4, 256>>>();
    hsum_kernel<<<256, 256>>>(h);
    tv_matvec_kernel<<<16, 512>>>(Wv, bv);   // Tv ready, independent of GEMM
    scan_A<<<NN / 8, 256>>>(A);
    dim3 ggrid(QKVD / BN, NN / BM, 3);       // 4 x 32 x 3
    qkv_gemm_tc<<<ggrid, 256>>>(h, Wq, bq, Wk, bk, Wv, bv);
    attn_kernel<<<NN, 128>>>(out);
}